// round 16
// baseline (speedup 1.0000x reference)
#include <cuda_runtime.h>
#include <cuda_fp16.h>
#include <cstdint>

// Problem constants (fixed by the reference)
#define NMAX   50000
#define EDIM   128
#define FIN    256
#define NEDGE  600000

// Scratch (no cudaMalloc allowed)
__device__ __half2 g_Th[(size_t)NMAX * 64];     // fp16 T = relu(F@W) @ v_w^T (64 half2/row)
__device__ __half  g_wth[FIN * EDIM];           // W^T as [n=128][k=256], half
__device__ __half  g_vwth[EDIM * EDIM];         // v_w as [n=128][k=128], half
__device__ int     g_deg[NMAX];
__device__ int     g_pos[NEDGE];                // intra-row rank of each edge
__device__ int     g_lrs[NMAX];                 // in-block exclusive scan of deg
__device__ int     g_bagg[64];                  // per-block aggregates
__device__ int     g_boff[64];                  // exclusive scan of aggregates
__device__ int2    g_csr[NEDGE];                // (col, weight-bits)
__device__ float   g_coef[2];
__device__ int     g_is64;

__device__ __forceinline__ uint32_t smem_u32(const void* p) {
    uint32_t a;
    asm("{ .reg .u64 t; cvta.to.shared.u64 t, %1; cvt.u32.u64 %0, t; }" : "=r"(a) : "l"(p));
    return a;
}
__device__ __forceinline__ void cpa16(uint32_t d, const void* s) {
    asm volatile("cp.async.cg.shared.global [%0], [%1], 16;" :: "r"(d), "l"(s) : "memory");
}
#define CPA_COMMIT() asm volatile("cp.async.commit_group;" ::: "memory")
#define CPA_WAIT0()  asm volatile("cp.async.wait_group 0;" ::: "memory")

// ---------------------------------------------------------------------------
// Fused prep: block 0 = detect + coef; 1..128 = W^T->half; 129..192 = v_w->half;
// 193.. = zero deg.
// detect: JAX x64-off silently downcasts int64->int32. Genuine int64 => first
// 64 values in [0,NMAX); int32 => packed pairs lo+(hi<<32) blow past NMAX.
// ---------------------------------------------------------------------------
__global__ void prep_kernel(const void* __restrict__ ei,
                            const float* __restrict__ lg, const float* __restrict__ mg,
                            const float* __restrict__ W, const float* __restrict__ VW,
                            int M) {
    int b = blockIdx.x, t = threadIdx.x;
    if (b == 0) {
        if (t == 0) {
            const long long* e64 = (const long long*)ei;
            int is64 = 1;
#pragma unroll 1
            for (int i = 0; i < 64; i++) {
                long long v = e64[i];
                if (v < 0 || v >= NMAX) { is64 = 0; break; }
            }
            g_is64 = is64;
        } else if (t == 32) {
            const float a0 = -1e-9f, a1 = 1.0f + 1e-9f;
            float a_low = 0.f, b_low = 0.f, a_mid = 0.f, c_mid = 0.f;
#pragma unroll
            for (int i = 0; i < 5; i++) {
                float g0 = fmaxf(lg[2 * i], 0.f), g1 = fmaxf(lg[2 * i + 1], 0.f);
                a_low += g0 * a0 + g1 * a1;
                b_low += g0 * (1.f - a0) + g1 * (1.f - a1);
                float m0 = fmaxf(mg[2 * i], 0.f), m1 = fmaxf(mg[2 * i + 1], 0.f);
                a_mid += m0 + m1;
                c_mid += m0 * a0 + m1 * a1;
            }
            g_coef[0] = a_low + a_mid;
            g_coef[1] = b_low - c_mid;
        }
    } else if (b <= 128) {
        int u = (b - 1) * 256 + t;           // 0..32767
        int n = u >> 8, k = u & 255;
        g_wth[n * FIN + k] = __float2half(W[k * EDIM + n]);
    } else if (b <= 192) {
        int u = (b - 129) * 256 + t;         // 0..16383
        g_vwth[u] = __float2half(VW[u]);
    } else {
        int u = (b - 193) * 256 + t;
        if (u < M) g_deg[u] = 0;
    }
}

// ---------------------------------------------------------------------------
// CSR build: histogram (saving intra-row rank) -> 2-level scan -> fill
// ---------------------------------------------------------------------------
__global__ __launch_bounds__(256) void hist_kernel(const void* __restrict__ ei, int ne, int M) {
    int e = blockIdx.x * blockDim.x + threadIdx.x;
    if (e >= ne) return;
    int r;
    if (g_is64) r = (int)((const long long*)ei)[e];
    else        r = ((const int*)ei)[e];
    if ((unsigned)r >= (unsigned)M) return;
    g_pos[e] = atomicAdd(&g_deg[r], 1);
}

// K1: per-1024-chunk smem scan. grid = ceil(M/1024) blocks x 1024 threads.
__global__ __launch_bounds__(1024) void scan1_kernel(int M) {
    __shared__ int part[1024];
    int t = threadIdx.x, i = blockIdx.x * 1024 + t;
    int v = (i < M) ? g_deg[i] : 0;
    part[t] = v;
    __syncthreads();
    for (int d = 1; d < 1024; d <<= 1) {
        int x = part[t];
        int y = (t >= d) ? part[t - d] : 0;
        __syncthreads();
        part[t] = x + y;
        __syncthreads();
    }
    if (i < M) g_lrs[i] = part[t] - v;     // exclusive within block
    if (t == 1023) g_bagg[blockIdx.x] = part[1023];
}

// K2: exclusive scan of <=64 block aggregates.
__global__ void scan2_kernel(int nb) {
    __shared__ int p[64];
    int t = threadIdx.x;
    int v = (t < nb) ? g_bagg[t] : 0;
    p[t] = v;
    __syncthreads();
    for (int d = 1; d < 64; d <<= 1) {
        int x = p[t];
        int y = (t >= d) ? p[t - d] : 0;
        __syncthreads();
        p[t] = x + y;
        __syncthreads();
    }
    if (t < nb) g_boff[t] = p[t] - v;
}

__global__ __launch_bounds__(256) void fill_kernel(const void* __restrict__ ei,
                                                   const float* __restrict__ ew,
                                                   int ne, int M) {
    int e = blockIdx.x * blockDim.x + threadIdx.x;
    if (e >= ne) return;
    int r, c;
    if (g_is64) {
        const long long* e64 = (const long long*)ei;
        r = (int)e64[e]; c = (int)e64[(size_t)ne + e];
    } else {
        const int* e32 = (const int*)ei;
        r = e32[e]; c = e32[(size_t)ne + e];
    }
    if ((unsigned)r >= (unsigned)M) return;
    float w = ew[e];
    if ((unsigned)c >= (unsigned)M) { c = 0; w = 0.f; }   // keep slot consistent
    int idx = g_lrs[r] + g_boff[r >> 10] + g_pos[e];
    if (idx < NEDGE) g_csr[idx] = make_int2(c, __float_as_int(w));
}

// ---------------------------------------------------------------------------
// fp16 mma.sync atom (m16n8k16, fp32 accumulate)
// ---------------------------------------------------------------------------
#define MMA_F16(d, a, b) \
    asm volatile("mma.sync.aligned.m16n8k16.row.col.f32.f16.f16.f32 " \
        "{%0,%1,%2,%3}, {%4,%5,%6,%7}, {%8,%9}, {%0,%1,%2,%3};" \
        : "+f"((d)[0]), "+f"((d)[1]), "+f"((d)[2]), "+f"((d)[3]) \
        : "r"((a)[0]), "r"((a)[1]), "r"((a)[2]), "r"((a)[3]), "r"((b)[0]), "r"((b)[1]))

// ---------------------------------------------------------------------------
// Fused B2B GEMM, fp16, 64x128 CTA tile.
// 8 warps of 32x32 -> acc halves to 32 regs -> 3 CTAs/SM (24 warps; the R14
// profile showed occ=21.7%, all pipes <30% => occupancy-latency-bound).
// R12 race-safe ordering kept (cp.async B prefetch issued post-barrier).
// SMEM bytes: A0@0 A1@5120 (64x40 half), B0@10240 B1@20480 (128x40 half),
// B2@30720 (128x136 half = 34816B), Ss@0 (64x136 half = 17408B, aliases the
// dead stage-1 A/B0 buffers). Total exactly 65536B -> 3 CTAs/SM.
// ---------------------------------------------------------------------------
#define ALD 40
#define SLD 136
#define A_B(b)  ((b) * 5120)
#define B_B(b)  (10240 + (b) * 10240)
#define B2_B    30720
#define DYN_SMEM 65536

__global__ __launch_bounds__(256, 3) void gemm_fused(const float* __restrict__ A, int M) {
    extern __shared__ char smem[];
    const uint32_t sb = smem_u32(smem);
    __half* Sh = (__half*)smem;

    const int tid = threadIdx.x, lane = tid & 31, wid = tid >> 5;
    const int gid = lane >> 2, tig = lane & 3;
    const int wm = wid >> 2, wn = wid & 3;     // 2 x 4 warp grid, 32x32 tiles
    const int m0 = blockIdx.x * 64;

    // --- prologue group: B2 (whole v_w) + stage-1 B chunk 0 ---
#pragma unroll
    for (int i = 0; i < 8; i++) {
        int u = tid + i * 256;                 // 0..2047 16B units
        int n = u >> 4, seg = u & 15;
        cpa16(sb + B2_B + (n * SLD + seg * 8) * 2, g_vwth + (size_t)n * EDIM + seg * 8);
    }
#pragma unroll
    for (int i = 0; i < 2; i++) {
        int u = tid * 2 + i;                   // 0..511 16B units
        int n = u >> 2, seg = u & 3;
        cpa16(sb + B_B(0) + (n * ALD + seg * 8) * 2, g_wth + (size_t)n * FIN + seg * 8);
    }
    CPA_COMMIT();

    // --- stage-1 A chunk 0: LDG fp32 -> cvt -> STS half (64 rows x 32 k) ---
    float4 areg[2];
#pragma unroll
    for (int i = 0; i < 2; i++) {
        int u = tid + i * 256;                 // 0..511 float4 units
        int r = u >> 3, c4 = (u & 7) * 4;
        int gm = m0 + r; if (gm >= M) gm = M - 1;
        areg[i] = *(const float4*)(A + (size_t)gm * FIN + c4);
    }
#pragma unroll
    for (int i = 0; i < 2; i++) {
        int u = tid + i * 256;
        int r = u >> 3, c4 = (u & 7) * 4;
        __half2 h01 = __floats2half2_rn(areg[i].x, areg[i].y);
        __half2 h23 = __floats2half2_rn(areg[i].z, areg[i].w);
        uint2 pk; pk.x = *(uint32_t*)&h01; pk.y = *(uint32_t*)&h23;
        *(uint2*)&Sh[(A_B(0) >> 1) + r * ALD + c4] = pk;
    }

    // ---------------- Stage 1: S = relu(F @ W), K=256, 8 chunks ----------------
    float acc[2][4][4] = {};

    for (int c = 0; c < 8; c++) {
        int cb = c & 1, nb = cb ^ 1;
        if (c < 7) {                           // LDG next A chunk (overlaps wait)
            int k0 = (c + 1) * 32;
#pragma unroll
            for (int i = 0; i < 2; i++) {
                int u = tid + i * 256;
                int r = u >> 3, c4 = (u & 7) * 4;
                int gm = m0 + r; if (gm >= M) gm = M - 1;
                areg[i] = *(const float4*)(A + (size_t)gm * FIN + k0 + c4);
            }
        }
        CPA_WAIT0();
        __syncthreads();                       // all reads of buffer nb done

        if (c < 7) {                           // SAFE: prefetch post-barrier
            int k0 = (c + 1) * 32;
#pragma unroll
            for (int i = 0; i < 2; i++) {
                int u = tid * 2 + i;
                int n = u >> 2, seg = u & 3;
                cpa16(sb + B_B(nb) + (n * ALD + seg * 8) * 2,
                      g_wth + (size_t)n * FIN + k0 + seg * 8);
            }
            CPA_COMMIT();
        }

        const __half* As = Sh + (A_B(cb) >> 1);
        const __half* Bs = Sh + (B_B(cb) >> 1);
#pragma unroll
        for (int s = 0; s < 2; s++) {
            int ks = s * 16;
            uint32_t a[2][4];
#pragma unroll
            for (int i = 0; i < 2; i++) {
                int r0 = wm * 32 + i * 16 + gid;
                a[i][0] = *(const uint32_t*)&As[r0 * ALD + ks + 2 * tig];
                a[i][1] = *(const uint32_t*)&As[(r0 + 8) * ALD + ks + 2 * tig];
                a[i][2] = *(const uint32_t*)&As[r0 * ALD + ks + 8 + 2 * tig];
                a[i][3] = *(const uint32_t*)&As[(r0 + 8) * ALD + ks + 8 + 2 * tig];
            }
#pragma unroll
            for (int j = 0; j < 4; j++) {
                int n0 = wn * 32 + j * 8 + gid;
                uint32_t b[2];
                b[0] = *(const uint32_t*)&Bs[n0 * ALD + ks + 2 * tig];
                b[1] = *(const uint32_t*)&Bs[n0 * ALD + ks + 8 + 2 * tig];
                MMA_F16(acc[0][j], a[0], b);
                MMA_F16(acc[1][j], a[1], b);
            }
        }

        if (c < 7) {                           // STS next A (safe post-barrier)
#pragma unroll
            for (int i = 0; i < 2; i++) {
                int u = tid + i * 256;
                int r = u >> 3, c4 = (u & 7) * 4;
                __half2 h01 = __floats2half2_rn(areg[i].x, areg[i].y);
                __half2 h23 = __floats2half2_rn(areg[i].z, areg[i].w);
                uint2 pk; pk.x = *(uint32_t*)&h01; pk.y = *(uint32_t*)&h23;
                *(uint2*)&Sh[(A_B(nb) >> 1) + r * ALD + c4] = pk;
            }
        }
    }
    __syncthreads();   // stage-1 buffers die; Ss overwrites them

    // Write S (relu, half) into Ss [m=64][128]
    __half* Ss = Sh;
#pragma unroll
    for (int i = 0; i < 2; i++) {
        int r0 = wm * 32 + i * 16 + gid;
        int r1 = r0 + 8;
#pragma unroll
        for (int j = 0; j < 4; j++) {
            int cc = wn * 32 + j * 8 + 2 * tig;
            __half2 h0 = __floats2half2_rn(fmaxf(acc[i][j][0], 0.f), fmaxf(acc[i][j][1], 0.f));
            __half2 h1 = __floats2half2_rn(fmaxf(acc[i][j][2], 0.f), fmaxf(acc[i][j][3], 0.f));
            *(uint32_t*)&Ss[r0 * SLD + cc] = *(uint32_t*)&h0;
            *(uint32_t*)&Ss[r1 * SLD + cc] = *(uint32_t*)&h1;
        }
    }
    __syncthreads();

    // ---------------- Stage 2: T = S @ v_w^T, K=128, sync-free ----------------
    const __half* B2 = Sh + (B2_B >> 1);
    float acc2[2][4][4] = {};
#pragma unroll
    for (int s = 0; s < 8; s++) {
        int ks = s * 16;
        uint32_t a[2][4];
#pragma unroll
        for (int i = 0; i < 2; i++) {
            int r0 = wm * 32 + i * 16 + gid;
            a[i][0] = *(const uint32_t*)&Ss[r0 * SLD + ks + 2 * tig];
            a[i][1] = *(const uint32_t*)&Ss[(r0 + 8) * SLD + ks + 2 * tig];
            a[i][2] = *(const uint32_t*)&Ss[r0 * SLD + ks + 8 + 2 * tig];
            a[i][3] = *(const uint32_t*)&Ss[(r0 + 8) * SLD + ks + 8 + 2 * tig];
        }
#pragma unroll
        for (int j = 0; j < 4; j++) {
            int n0 = wn * 32 + j * 8 + gid;
            uint32_t b[2];
            b[0] = *(const uint32_t*)&B2[n0 * SLD + ks + 2 * tig];
            b[1] = *(const uint32_t*)&B2[n0 * SLD + ks + 8 + 2 * tig];
            MMA_F16(acc2[0][j], a[0], b);
            MMA_F16(acc2[1][j], a[1], b);
        }
    }

    // Store fp16 mirror only
#pragma unroll
    for (int i = 0; i < 2; i++) {
        int r0 = m0 + wm * 32 + i * 16 + gid;
        int r1 = r0 + 8;
#pragma unroll
        for (int j = 0; j < 4; j++) {
            int cc = wn * 32 + j * 8 + 2 * tig;
            if (r0 < M)
                g_Th[(size_t)r0 * 64 + (cc >> 1)] = __floats2half2_rn(acc2[i][j][0], acc2[i][j][1]);
            if (r1 < M)
                g_Th[(size_t)r1 * 64 + (cc >> 1)] = __floats2half2_rn(acc2[i][j][2], acc2[i][j][3]);
        }
    }
}

// ---------------------------------------------------------------------------
// Gather + finalize: out[r] = sA * sum_e w_e * Th[col_e] + sB * Th[r] + 2*v_b
// One warp per row; lane owns 4 cols; unroll-2 (unroll-4 regressed occupancy).
// ---------------------------------------------------------------------------
__global__ __launch_bounds__(256) void gather_kernel(const float* __restrict__ VB,
                                                     float* __restrict__ out, int M) {
    int wr   = (blockIdx.x * blockDim.x + threadIdx.x) >> 5;
    int lane = threadIdx.x & 31;
    if (wr >= M) return;
    int beg = g_lrs[wr] + g_boff[wr >> 10];
    int end = beg + g_deg[wr];
    float4 acc = make_float4(0.f, 0.f, 0.f, 0.f);
    int i = beg;
    for (; i + 2 <= end; i += 2) {
        int2 e0 = g_csr[i], e1 = g_csr[i + 1];
        uint2 h0 = ((const uint2*)(g_Th + (size_t)e0.x * 64))[lane];
        uint2 h1 = ((const uint2*)(g_Th + (size_t)e1.x * 64))[lane];
        float w0 = __int_as_float(e0.y), w1 = __int_as_float(e1.y);
        float2 a0 = __half22float2(*(__half2*)&h0.x), b0 = __half22float2(*(__half2*)&h0.y);
        float2 a1 = __half22float2(*(__half2*)&h1.x), b1 = __half22float2(*(__half2*)&h1.y);
        acc.x += w0 * a0.x + w1 * a1.x;
        acc.y += w0 * a0.y + w1 * a1.y;
        acc.z += w0 * b0.x + w1 * b1.x;
        acc.w += w0 * b0.y + w1 * b1.y;
    }
    if (i < end) {
        int2 e0 = g_csr[i];
        uint2 h0 = ((const uint2*)(g_Th + (size_t)e0.x * 64))[lane];
        float w0 = __int_as_float(e0.y);
        float2 a0 = __half22float2(*(__half2*)&h0.x), b0 = __half22float2(*(__half2*)&h0.y);
        acc.x += w0 * a0.x; acc.y += w0 * a0.y; acc.z += w0 * b0.x; acc.w += w0 * b0.y;
    }
    const float sA = g_coef[0], sB = g_coef[1];
    uint2 hs = ((const uint2*)(g_Th + (size_t)wr * 64))[lane];
    float2 ta = __half22float2(*(__half2*)&hs.x), tb = __half22float2(*(__half2*)&hs.y);
    float4 b = __ldg(((const float4*)VB) + lane);
    float4 o;
    o.x = sA * acc.x + sB * ta.x + 2.0f * b.x;
    o.y = sA * acc.y + sB * ta.y + 2.0f * b.y;
    o.z = sA * acc.z + sB * tb.x + 2.0f * b.z;
    o.w = sA * acc.w + sB * tb.y + 2.0f * b.w;
    ((float4*)(out + (size_t)wr * EDIM))[lane] = o;
}

// ---------------------------------------------------------------------------
// kernel_launch
// Inputs: 0 feature, 1 edge_index, 2 edge_weight, 3 weight, 4 low_gamma,
//         5 mid_gamma, 6 q_w, 7 q_b, 8 k_w, 9 k_b, 10 v_w, 11 v_b
// q/k branch is dead (softmax over query axis then sum over query axis => 1).
// Reassociation: out = sA*(A_sp@T) + sB*T + 2vb with T = relu(F@W)@v_w^T.
// ---------------------------------------------------------------------------
extern "C" void kernel_launch(void* const* d_in, const int* in_sizes, int n_in,
                              void* d_out, int out_size) {
    const float* feature = (const float*)d_in[0];
    const void*  ei      = d_in[1];
    const float* ew      = (const float*)d_in[2];
    const float* weight  = (const float*)d_in[3];
    const float* lg      = (const float*)d_in[4];
    const float* mg      = (const float*)d_in[5];
    const float* vw      = (const float*)d_in[10];
    const float* vb      = (const float*)d_in[11];
    float*       out     = (float*)d_out;

    const int M  = in_sizes[0] / FIN;     // 50000
    const int ne = in_sizes[2];           // 600000

    static int smem_set = 0;
    if (!smem_set) {
        cudaFuncSetAttribute(gemm_fused, cudaFuncAttributeMaxDynamicSharedMemorySize, DYN_SMEM);
        smem_set = 1;
    }

    int zero_blocks = (M + 255) / 256;
    prep_kernel<<<193 + zero_blocks, 256>>>(ei, lg, mg, weight, vw, M);

    int eblocks = (ne + 255) / 256;
    hist_kernel<<<eblocks, 256>>>(ei, ne, M);

    int nb = (M + 1023) / 1024;           // 49 blocks
    scan1_kernel<<<nb, 1024>>>(M);

    int gemm_blocks = (M + 63) / 64;      // 782 (profiled slot #4)
    gemm_fused<<<gemm_blocks, 256, DYN_SMEM>>>(feature, M);

    scan2_kernel<<<1, 64>>>(nb);

    fill_kernel<<<eblocks, 256>>>(ei, ew, ne, M);

    int gather_blocks = (M * 32 + 255) / 256;
    gather_kernel<<<gather_blocks, 256>>>(vb, out, M);
}

// round 17
// speedup vs baseline: 1.2000x; 1.2000x over previous
#include <cuda_runtime.h>
#include <cuda_fp16.h>
#include <cstdint>

// Problem constants (fixed by the reference)
#define NMAX   50000
#define EDIM   128
#define FIN    256
#define NEDGE  600000

// Scratch (no cudaMalloc allowed)
__device__ __half2 g_Th[(size_t)NMAX * 64];     // fp16 T = relu(F@W) @ v_w^T (64 half2/row)
__device__ __half  g_wth[FIN * EDIM];           // W^T as [n=128][k=256], half
__device__ __half  g_vwth[EDIM * EDIM];         // v_w as [n=128][k=128], half
__device__ int     g_deg[NMAX];
__device__ int     g_pos[NEDGE];                // intra-row rank of each edge
__device__ int     g_lrs[NMAX];                 // in-block exclusive scan of deg
__device__ int     g_bagg[64];                  // per-block aggregates
__device__ int     g_boff[64];                  // exclusive scan of aggregates
__device__ int2    g_csr[NEDGE];                // (col, weight-bits)
__device__ float   g_coef[2];
__device__ int     g_is64;

__device__ __forceinline__ uint32_t smem_u32(const void* p) {
    uint32_t a;
    asm("{ .reg .u64 t; cvta.to.shared.u64 t, %1; cvt.u32.u64 %0, t; }" : "=r"(a) : "l"(p));
    return a;
}
__device__ __forceinline__ void cpa16(uint32_t d, const void* s) {
    asm volatile("cp.async.cg.shared.global [%0], [%1], 16;" :: "r"(d), "l"(s) : "memory");
}
#define CPA_COMMIT() asm volatile("cp.async.commit_group;" ::: "memory")
#define CPA_WAIT0()  asm volatile("cp.async.wait_group 0;" ::: "memory")

// ---------------------------------------------------------------------------
// Fused prep: block 0 = detect + coef; 1..128 = W^T->half; 129..192 = v_w->half;
// 193.. = zero deg.
// detect: JAX x64-off silently downcasts int64->int32. Genuine int64 => first
// 64 values in [0,NMAX); int32 => packed pairs lo+(hi<<32) blow past NMAX.
// ---------------------------------------------------------------------------
__global__ void prep_kernel(const void* __restrict__ ei,
                            const float* __restrict__ lg, const float* __restrict__ mg,
                            const float* __restrict__ W, const float* __restrict__ VW,
                            int M) {
    int b = blockIdx.x, t = threadIdx.x;
    if (b == 0) {
        if (t == 0) {
            const long long* e64 = (const long long*)ei;
            int is64 = 1;
#pragma unroll 1
            for (int i = 0; i < 64; i++) {
                long long v = e64[i];
                if (v < 0 || v >= NMAX) { is64 = 0; break; }
            }
            g_is64 = is64;
        } else if (t == 32) {
            const float a0 = -1e-9f, a1 = 1.0f + 1e-9f;
            float a_low = 0.f, b_low = 0.f, a_mid = 0.f, c_mid = 0.f;
#pragma unroll
            for (int i = 0; i < 5; i++) {
                float g0 = fmaxf(lg[2 * i], 0.f), g1 = fmaxf(lg[2 * i + 1], 0.f);
                a_low += g0 * a0 + g1 * a1;
                b_low += g0 * (1.f - a0) + g1 * (1.f - a1);
                float m0 = fmaxf(mg[2 * i], 0.f), m1 = fmaxf(mg[2 * i + 1], 0.f);
                a_mid += m0 + m1;
                c_mid += m0 * a0 + m1 * a1;
            }
            g_coef[0] = a_low + a_mid;
            g_coef[1] = b_low - c_mid;
        }
    } else if (b <= 128) {
        int u = (b - 1) * 256 + t;           // 0..32767
        int n = u >> 8, k = u & 255;
        g_wth[n * FIN + k] = __float2half(W[k * EDIM + n]);
    } else if (b <= 192) {
        int u = (b - 129) * 256 + t;         // 0..16383
        g_vwth[u] = __float2half(VW[u]);
    } else {
        int u = (b - 193) * 256 + t;
        if (u < M) g_deg[u] = 0;
    }
}

// ---------------------------------------------------------------------------
// CSR build: histogram (saving intra-row rank) -> 2-level scan -> fill
// ---------------------------------------------------------------------------
__global__ __launch_bounds__(256) void hist_kernel(const void* __restrict__ ei, int ne, int M) {
    int e = blockIdx.x * blockDim.x + threadIdx.x;
    if (e >= ne) return;
    int r;
    if (g_is64) r = (int)((const long long*)ei)[e];
    else        r = ((const int*)ei)[e];
    if ((unsigned)r >= (unsigned)M) return;
    g_pos[e] = atomicAdd(&g_deg[r], 1);
}

// K1: per-1024-chunk smem scan. grid = ceil(M/1024) blocks x 1024 threads.
__global__ __launch_bounds__(1024) void scan1_kernel(int M) {
    __shared__ int part[1024];
    int t = threadIdx.x, i = blockIdx.x * 1024 + t;
    int v = (i < M) ? g_deg[i] : 0;
    part[t] = v;
    __syncthreads();
    for (int d = 1; d < 1024; d <<= 1) {
        int x = part[t];
        int y = (t >= d) ? part[t - d] : 0;
        __syncthreads();
        part[t] = x + y;
        __syncthreads();
    }
    if (i < M) g_lrs[i] = part[t] - v;     // exclusive within block
    if (t == 1023) g_bagg[blockIdx.x] = part[1023];
}

// K2: exclusive scan of <=64 block aggregates.
__global__ void scan2_kernel(int nb) {
    __shared__ int p[64];
    int t = threadIdx.x;
    int v = (t < nb) ? g_bagg[t] : 0;
    p[t] = v;
    __syncthreads();
    for (int d = 1; d < 64; d <<= 1) {
        int x = p[t];
        int y = (t >= d) ? p[t - d] : 0;
        __syncthreads();
        p[t] = x + y;
        __syncthreads();
    }
    if (t < nb) g_boff[t] = p[t] - v;
}

__global__ __launch_bounds__(256) void fill_kernel(const void* __restrict__ ei,
                                                   const float* __restrict__ ew,
                                                   int ne, int M) {
    int e = blockIdx.x * blockDim.x + threadIdx.x;
    if (e >= ne) return;
    int r, c;
    if (g_is64) {
        const long long* e64 = (const long long*)ei;
        r = (int)e64[e]; c = (int)e64[(size_t)ne + e];
    } else {
        const int* e32 = (const int*)ei;
        r = e32[e]; c = e32[(size_t)ne + e];
    }
    if ((unsigned)r >= (unsigned)M) return;
    float w = ew[e];
    if ((unsigned)c >= (unsigned)M) { c = 0; w = 0.f; }   // keep slot consistent
    int idx = g_lrs[r] + g_boff[r >> 10] + g_pos[e];
    if (idx < NEDGE) g_csr[idx] = make_int2(c, __float_as_int(w));
}

// ---------------------------------------------------------------------------
// fp16 mma.sync atom (m16n8k16, fp32 accumulate)
// ---------------------------------------------------------------------------
#define MMA_F16(d, a, b) \
    asm volatile("mma.sync.aligned.m16n8k16.row.col.f32.f16.f16.f32 " \
        "{%0,%1,%2,%3}, {%4,%5,%6,%7}, {%8,%9}, {%0,%1,%2,%3};" \
        : "+f"((d)[0]), "+f"((d)[1]), "+f"((d)[2]), "+f"((d)[3]) \
        : "r"((a)[0]), "r"((a)[1]), "r"((a)[2]), "r"((a)[3]), "r"((b)[0]), "r"((b)[1]))

// ---------------------------------------------------------------------------
// Fused B2B GEMM, fp16, 128x128 CTA tile (R14 config — measured 30.75us; the
// R16 64x128 experiment raised occupancy but lowered per-warp efficiency and
// regressed to 35.4us, so this is the local optimum).
// R12 race-safe ordering (cp.async B prefetch issued post-barrier).
// SMEM: A0@0 A1@10240 B0@20480 B1@30720 (each 128x40 half),
// B2@40960 (128x136 half, whole v_w once), Ss@0 (128x136, aliases stage-1).
// ---------------------------------------------------------------------------
#define ALD 40
#define SLD 136
#define A_B(b)  ((b) * 10240)
#define B_B(b)  (20480 + (b) * 10240)
#define B2_B    40960
#define DYN_SMEM 75776

__global__ __launch_bounds__(256) void gemm_fused(const float* __restrict__ A, int M) {
    extern __shared__ char smem[];
    const uint32_t sb = smem_u32(smem);
    __half* Sh = (__half*)smem;

    const int tid = threadIdx.x, lane = tid & 31, wid = tid >> 5;
    const int gid = lane >> 2, tig = lane & 3;
    const int wm = wid >> 1, wn = wid & 1;
    const int m0 = blockIdx.x * 128;

    // --- prologue group: B2 (whole v_w) + stage-1 B chunk 0 ---
#pragma unroll
    for (int i = 0; i < 8; i++) {
        int u = tid + i * 256;
        int n = u >> 4, seg = u & 15;
        cpa16(sb + B2_B + (n * SLD + seg * 8) * 2, g_vwth + (size_t)n * EDIM + seg * 8);
    }
#pragma unroll
    for (int i = 0; i < 2; i++) {
        int u = tid * 2 + i;
        int n = u >> 2, seg = u & 3;
        cpa16(sb + B_B(0) + (n * ALD + seg * 8) * 2, g_wth + (size_t)n * FIN + seg * 8);
    }
    CPA_COMMIT();

    // --- stage-1 A chunk 0: LDG fp32 -> cvt -> STS half ---
    float4 areg[4];
#pragma unroll
    for (int i = 0; i < 4; i++) {
        int u = tid + i * 256;
        int r = u >> 3, c4 = (u & 7) * 4;
        int gm = m0 + r; if (gm >= M) gm = M - 1;
        areg[i] = *(const float4*)(A + (size_t)gm * FIN + c4);
    }
#pragma unroll
    for (int i = 0; i < 4; i++) {
        int u = tid + i * 256;
        int r = u >> 3, c4 = (u & 7) * 4;
        __half2 h01 = __floats2half2_rn(areg[i].x, areg[i].y);
        __half2 h23 = __floats2half2_rn(areg[i].z, areg[i].w);
        uint2 pk; pk.x = *(uint32_t*)&h01; pk.y = *(uint32_t*)&h23;
        *(uint2*)&Sh[(A_B(0) >> 1) + r * ALD + c4] = pk;
    }

    // ---------------- Stage 1: S = relu(F @ W), K=256, 8 chunks ----------------
    float acc[2][8][4] = {};

    for (int c = 0; c < 8; c++) {
        int cb = c & 1, nb = cb ^ 1;
        if (c < 7) {                         // LDG next A chunk (overlaps wait)
            int k0 = (c + 1) * 32;
#pragma unroll
            for (int i = 0; i < 4; i++) {
                int u = tid + i * 256;
                int r = u >> 3, c4 = (u & 7) * 4;
                int gm = m0 + r; if (gm >= M) gm = M - 1;
                areg[i] = *(const float4*)(A + (size_t)gm * FIN + k0 + c4);
            }
        }
        CPA_WAIT0();
        __syncthreads();                     // all reads of buffer nb done

        if (c < 7) {                         // SAFE: prefetch post-barrier
            int k0 = (c + 1) * 32;
#pragma unroll
            for (int i = 0; i < 2; i++) {
                int u = tid * 2 + i;
                int n = u >> 2, seg = u & 3;
                cpa16(sb + B_B(nb) + (n * ALD + seg * 8) * 2,
                      g_wth + (size_t)n * FIN + k0 + seg * 8);
            }
            CPA_COMMIT();
        }

        const __half* As = Sh + (A_B(cb) >> 1);
        const __half* Bs = Sh + (B_B(cb) >> 1);
#pragma unroll
        for (int s = 0; s < 2; s++) {
            int ks = s * 16;
            uint32_t a[2][4];
#pragma unroll
            for (int i = 0; i < 2; i++) {
                int r0 = wm * 32 + i * 16 + gid;
                a[i][0] = *(const uint32_t*)&As[r0 * ALD + ks + 2 * tig];
                a[i][1] = *(const uint32_t*)&As[(r0 + 8) * ALD + ks + 2 * tig];
                a[i][2] = *(const uint32_t*)&As[r0 * ALD + ks + 8 + 2 * tig];
                a[i][3] = *(const uint32_t*)&As[(r0 + 8) * ALD + ks + 8 + 2 * tig];
            }
#pragma unroll
            for (int j = 0; j < 8; j++) {
                int n0 = wn * 64 + j * 8 + gid;
                uint32_t b[2];
                b[0] = *(const uint32_t*)&Bs[n0 * ALD + ks + 2 * tig];
                b[1] = *(const uint32_t*)&Bs[n0 * ALD + ks + 8 + 2 * tig];
                MMA_F16(acc[0][j], a[0], b);
                MMA_F16(acc[1][j], a[1], b);
            }
        }

        if (c < 7) {                         // STS next A (safe post-barrier)
#pragma unroll
            for (int i = 0; i < 4; i++) {
                int u = tid + i * 256;
                int r = u >> 3, c4 = (u & 7) * 4;
                __half2 h01 = __floats2half2_rn(areg[i].x, areg[i].y);
                __half2 h23 = __floats2half2_rn(areg[i].z, areg[i].w);
                uint2 pk; pk.x = *(uint32_t*)&h01; pk.y = *(uint32_t*)&h23;
                *(uint2*)&Sh[(A_B(nb) >> 1) + r * ALD + c4] = pk;
            }
        }
    }
    __syncthreads();   // stage-1 buffers die; Ss overwrites them

    // Write S (relu, half) into Ss [m][128]
    __half* Ss = Sh;
#pragma unroll
    for (int i = 0; i < 2; i++) {
        int r0 = wm * 32 + i * 16 + gid;
        int r1 = r0 + 8;
#pragma unroll
        for (int j = 0; j < 8; j++) {
            int cc = wn * 64 + j * 8 + 2 * tig;
            __half2 h0 = __floats2half2_rn(fmaxf(acc[i][j][0], 0.f), fmaxf(acc[i][j][1], 0.f));
            __half2 h1 = __floats2half2_rn(fmaxf(acc[i][j][2], 0.f), fmaxf(acc[i][j][3], 0.f));
            *(uint32_t*)&Ss[r0 * SLD + cc] = *(uint32_t*)&h0;
            *(uint32_t*)&Ss[r1 * SLD + cc] = *(uint32_t*)&h1;
        }
    }
    __syncthreads();

    // ---------------- Stage 2: T = S @ v_w^T, K=128, sync-free ----------------
    const __half* B2 = Sh + (B2_B >> 1);
    float acc2[2][8][4] = {};
#pragma unroll
    for (int s = 0; s < 8; s++) {
        int ks = s * 16;
        uint32_t a[2][4];
#pragma unroll
        for (int i = 0; i < 2; i++) {
            int r0 = wm * 32 + i * 16 + gid;
            a[i][0] = *(const uint32_t*)&Ss[r0 * SLD + ks + 2 * tig];
            a[i][1] = *(const uint32_t*)&Ss[(r0 + 8) * SLD + ks + 2 * tig];
            a[i][2] = *(const uint32_t*)&Ss[r0 * SLD + ks + 8 + 2 * tig];
            a[i][3] = *(const uint32_t*)&Ss[(r0 + 8) * SLD + ks + 8 + 2 * tig];
        }
#pragma unroll
        for (int j = 0; j < 8; j++) {
            int n0 = wn * 64 + j * 8 + gid;
            uint32_t b[2];
            b[0] = *(const uint32_t*)&B2[n0 * SLD + ks + 2 * tig];
            b[1] = *(const uint32_t*)&B2[n0 * SLD + ks + 8 + 2 * tig];
            MMA_F16(acc2[0][j], a[0], b);
            MMA_F16(acc2[1][j], a[1], b);
        }
    }

    // Store fp16 mirror only
#pragma unroll
    for (int i = 0; i < 2; i++) {
        int r0 = m0 + wm * 32 + i * 16 + gid;
        int r1 = r0 + 8;
#pragma unroll
        for (int j = 0; j < 8; j++) {
            int cc = wn * 64 + j * 8 + 2 * tig;
            if (r0 < M)
                g_Th[(size_t)r0 * 64 + (cc >> 1)] = __floats2half2_rn(acc2[i][j][0], acc2[i][j][1]);
            if (r1 < M)
                g_Th[(size_t)r1 * 64 + (cc >> 1)] = __floats2half2_rn(acc2[i][j][2], acc2[i][j][3]);
        }
    }
}

// ---------------------------------------------------------------------------
// Gather + finalize: out[r] = sA * sum_e w_e * Th[col_e] + sB * Th[r] + 2*v_b
// One warp per row; lane owns 4 cols; unroll-2.
// ---------------------------------------------------------------------------
__global__ __launch_bounds__(256) void gather_kernel(const float* __restrict__ VB,
                                                     float* __restrict__ out, int M) {
    int wr   = (blockIdx.x * blockDim.x + threadIdx.x) >> 5;
    int lane = threadIdx.x & 31;
    if (wr >= M) return;
    int beg = g_lrs[wr] + g_boff[wr >> 10];
    int end = beg + g_deg[wr];
    float4 acc = make_float4(0.f, 0.f, 0.f, 0.f);
    int i = beg;
    for (; i + 2 <= end; i += 2) {
        int2 e0 = g_csr[i], e1 = g_csr[i + 1];
        uint2 h0 = ((const uint2*)(g_Th + (size_t)e0.x * 64))[lane];
        uint2 h1 = ((const uint2*)(g_Th + (size_t)e1.x * 64))[lane];
        float w0 = __int_as_float(e0.y), w1 = __int_as_float(e1.y);
        float2 a0 = __half22float2(*(__half2*)&h0.x), b0 = __half22float2(*(__half2*)&h0.y);
        float2 a1 = __half22float2(*(__half2*)&h1.x), b1 = __half22float2(*(__half2*)&h1.y);
        acc.x += w0 * a0.x + w1 * a1.x;
        acc.y += w0 * a0.y + w1 * a1.y;
        acc.z += w0 * b0.x + w1 * b1.x;
        acc.w += w0 * b0.y + w1 * b1.y;
    }
    if (i < end) {
        int2 e0 = g_csr[i];
        uint2 h0 = ((const uint2*)(g_Th + (size_t)e0.x * 64))[lane];
        float w0 = __int_as_float(e0.y);
        float2 a0 = __half22float2(*(__half2*)&h0.x), b0 = __half22float2(*(__half2*)&h0.y);
        acc.x += w0 * a0.x; acc.y += w0 * a0.y; acc.z += w0 * b0.x; acc.w += w0 * b0.y;
    }
    const float sA = g_coef[0], sB = g_coef[1];
    uint2 hs = ((const uint2*)(g_Th + (size_t)wr * 64))[lane];
    float2 ta = __half22float2(*(__half2*)&hs.x), tb = __half22float2(*(__half2*)&hs.y);
    float4 b = __ldg(((const float4*)VB) + lane);
    float4 o;
    o.x = sA * acc.x + sB * ta.x + 2.0f * b.x;
    o.y = sA * acc.y + sB * ta.y + 2.0f * b.y;
    o.z = sA * acc.z + sB * tb.x + 2.0f * b.z;
    o.w = sA * acc.w + sB * tb.y + 2.0f * b.w;
    ((float4*)(out + (size_t)wr * EDIM))[lane] = o;
}

// ---------------------------------------------------------------------------
// kernel_launch
// Inputs: 0 feature, 1 edge_index, 2 edge_weight, 3 weight, 4 low_gamma,
//         5 mid_gamma, 6 q_w, 7 q_b, 8 k_w, 9 k_b, 10 v_w, 11 v_b
// q/k branch is dead (softmax over query axis then sum over query axis => 1).
// Reassociation: out = sA*(A_sp@T) + sB*T + 2vb with T = relu(F@W)@v_w^T.
// R17: gemm_fused runs on a forked stream, overlapping the independent CSR
// chain (hist/scan/fill) — event fork/join is graph-capturable. Falls back
// to the serial order if stream/event creation is unavailable.
// ---------------------------------------------------------------------------
extern "C" void kernel_launch(void* const* d_in, const int* in_sizes, int n_in,
                              void* d_out, int out_size) {
    const float* feature = (const float*)d_in[0];
    const void*  ei      = d_in[1];
    const float* ew      = (const float*)d_in[2];
    const float* lg      = (const float*)d_in[4];
    const float* mg      = (const float*)d_in[5];
    const float* weight  = (const float*)d_in[3];
    const float* vw      = (const float*)d_in[10];
    const float* vb      = (const float*)d_in[11];
    float*       out     = (float*)d_out;

    const int M  = in_sizes[0] / FIN;     // 50000
    const int ne = in_sizes[2];           // 600000

    static int init_done = 0;
    static cudaStream_t s2 = 0;
    static cudaEvent_t evFork = 0, evJoin = 0;
    if (!init_done) {
        init_done = 1;
        cudaFuncSetAttribute(gemm_fused, cudaFuncAttributeMaxDynamicSharedMemorySize, DYN_SMEM);
        if (cudaStreamCreateWithFlags(&s2, cudaStreamNonBlocking) != cudaSuccess) { s2 = 0; }
        if (s2) {
            if (cudaEventCreateWithFlags(&evFork, cudaEventDisableTiming) != cudaSuccess ||
                cudaEventCreateWithFlags(&evJoin, cudaEventDisableTiming) != cudaSuccess) {
                s2 = 0;
            }
        }
    }

    int zero_blocks  = (M + 255) / 256;
    int eblocks      = (ne + 255) / 256;
    int nb           = (M + 1023) / 1024;   // 49
    int gemm_blocks  = (M + 127) / 128;     // 391
    int gather_blocks = (M * 32 + 255) / 256;

    prep_kernel<<<193 + zero_blocks, 256>>>(ei, lg, mg, weight, vw, M);

    if (s2) {
        // Fork: gemm (depends only on prep) runs on s2, CSR chain on default.
        cudaEventRecord(evFork, 0);
        cudaStreamWaitEvent(s2, evFork, 0);
        gemm_fused<<<gemm_blocks, 256, DYN_SMEM, s2>>>(feature, M);
        cudaEventRecord(evJoin, s2);

        hist_kernel<<<eblocks, 256>>>(ei, ne, M);
        scan1_kernel<<<nb, 1024>>>(M);
        scan2_kernel<<<1, 64>>>(nb);
        fill_kernel<<<eblocks, 256>>>(ei, ew, ne, M);

        // Join: gather needs both T (s2) and CSR (default).
        cudaStreamWaitEvent(0, evJoin, 0);
        gather_kernel<<<gather_blocks, 256>>>(vb, out, M);
    } else {
        hist_kernel<<<eblocks, 256>>>(ei, ne, M);
        scan1_kernel<<<nb, 1024>>>(M);
        gemm_fused<<<gemm_blocks, 256, DYN_SMEM>>>(feature, M);
        scan2_kernel<<<1, 64>>>(nb);
        fill_kernel<<<eblocks, 256>>>(ei, ew, ne, M);
        gather_kernel<<<gather_blocks, 256>>>(vb, out, M);
    }
}